// round 3
// baseline (speedup 1.0000x reference)
#include <cuda_runtime.h>
#include <cstdint>

#define N_NODES 100000
#define N_EDGES 2048
#define L_TOK 8
#define HID 64
#define D_IN 512      // L_TOK * HID
#define D_GNN 128
#define VOCAB 32000
#define FFN_D 256
#define NROWS (N_EDGES * 2)   // 4096 lm-head rows
#define LBL_OFF 16384         // labels occupy [0, 16384)

// ---------------- device scratch (no allocations allowed) ----------------
__device__ float g_agg[N_NODES * D_GNN];    // only dst rows ever touched
__device__ float g_edge_h[N_EDGES * D_GNN];
__device__ float g_x[NROWS * HID];
__device__ float g_rowsum[NROWS];

// ---------------- K0: zero touched agg rows + row sums ----------------
__global__ void k0_zero(const int* __restrict__ edge_index) {
    int b = blockIdx.x, t = threadIdx.x;
    if (b < N_EDGES) {
        int dst = edge_index[N_EDGES + b];
        g_agg[dst * D_GNN + t] = 0.f;
    } else {
        int i = (b - N_EDGES) * 128 + t;
        if (i < NROWS) g_rowsum[i] = 0.f;
    }
}

// ---------------- K1: msg = (node_emb[src] + edge_emb) @ W_nbr; scatter-add at dst ----------------
__global__ void k1_msg(const int* __restrict__ node_tokens,
                       const int* __restrict__ edge_tokens,
                       const int* __restrict__ edge_index,
                       const float* __restrict__ emb,
                       const float* __restrict__ W_nbr) {
    __shared__ float t_s[16][D_IN];
    __shared__ int s_src[16], s_dst[16];
    int b = blockIdx.x, tid = threadIdx.x;
    int e0 = b * 16;
    if (tid < 16) {
        s_src[tid] = edge_index[e0 + tid];
        s_dst[tid] = edge_index[N_EDGES + e0 + tid];
    }
    __syncthreads();
    for (int el = 0; el < 16; el++) {
        int e = e0 + el;
        int sn = s_src[el];
        for (int idx = tid; idx < D_IN; idx += 128) {
            int l = idx >> 6, h = idx & 63;
            int tn = node_tokens[sn * L_TOK + l];
            int te = edge_tokens[e * L_TOK + l];
            t_s[el][idx] = emb[tn * HID + h] + emb[te * HID + h];
        }
    }
    __syncthreads();
    float acc[16];
#pragma unroll
    for (int el = 0; el < 16; el++) acc[el] = 0.f;
    for (int k = 0; k < D_IN; k++) {
        float w = W_nbr[k * D_GNN + tid];
#pragma unroll
        for (int el = 0; el < 16; el++) acc[el] += t_s[el][k] * w;
    }
#pragma unroll
    for (int el = 0; el < 16; el++)
        atomicAdd(&g_agg[s_dst[el] * D_GNN + tid], acc[el]);
}

// ---------------- K2: h = relu(node_emb @ W_self + agg) at endpoints; edge_h = h_src+h_dst ----------------
__global__ void k2_h(const int* __restrict__ node_tokens,
                     const int* __restrict__ edge_index,
                     const float* __restrict__ emb,
                     const float* __restrict__ W_self) {
    __shared__ float ne[16][D_IN];
    __shared__ int s_node[16];
    int b = blockIdx.x, tid = threadIdx.x;
    int e0 = b * 8;
    if (tid < 16) {
        int el = tid & 7;
        s_node[tid] = (tid < 8) ? edge_index[e0 + el] : edge_index[N_EDGES + e0 + el];
    }
    __syncthreads();
    for (int r = 0; r < 16; r++) {
        int n = s_node[r];
        for (int idx = tid; idx < D_IN; idx += 128) {
            int l = idx >> 6, h = idx & 63;
            int tn = node_tokens[n * L_TOK + l];
            ne[r][idx] = emb[tn * HID + h];
        }
    }
    __syncthreads();
    float acc[16];
#pragma unroll
    for (int r = 0; r < 16; r++) acc[r] = 0.f;
    for (int k = 0; k < D_IN; k++) {
        float w = W_self[k * D_GNN + tid];
#pragma unroll
        for (int r = 0; r < 16; r++) acc[r] += ne[r][k] * w;
    }
#pragma unroll
    for (int el = 0; el < 8; el++) {
        float hs = fmaxf(acc[el]     + g_agg[s_node[el]     * D_GNN + tid], 0.f);
        float hd = fmaxf(acc[el + 8] + g_agg[s_node[el + 8] * D_GNN + tid], 0.f);
        g_edge_h[(e0 + el) * D_GNN + tid] = hs + hd;
    }
}

// ---------------- K3: transformer block — warp per (edge,seq) row, smem broadcast, split chains ----------------
__global__ __launch_bounds__(256) void k3_xform(const float* __restrict__ Wq, const float* __restrict__ Wk,
                                                const float* __restrict__ Wv, const float* __restrict__ Wo,
                                                const float* __restrict__ W1, const float* __restrict__ W2) {
    __shared__ float xsm[8][64];
    __shared__ float ksm[4][2][64];
    __shared__ float vsm[4][2][64];
    __shared__ float hsm[8][FFN_D];
    int tid = threadIdx.x, lane = tid & 31, wid = tid >> 5;
    int el = wid >> 1, s = wid & 1;
    int e = blockIdx.x * 4 + el;

    const float2* xg = (const float2*)g_edge_h;
    float2 xv = xg[e * 64 + s * 32 + lane];
    float x0 = xv.x, x1 = xv.y;   // this lane owns cols 2*lane, 2*lane+1
    xsm[wid][2 * lane] = x0;
    xsm[wid][2 * lane + 1] = x1;
    __syncwarp();

    const float2* Wq2 = (const float2*)Wq;
    const float2* Wk2 = (const float2*)Wk;
    const float2* Wv2 = (const float2*)Wv;
    const float2* Wo2 = (const float2*)Wo;
    const float2* W22 = (const float2*)W2;

    // q,k,v: 6 independent accumulator pairs, x broadcast from smem (not in dep chain)
    float q0 = 0.f, q1 = 0.f, kk0 = 0.f, kk1 = 0.f, v0 = 0.f, v1 = 0.f;
    float q0b = 0.f, q1b = 0.f, kk0b = 0.f, kk1b = 0.f, v0b = 0.f, v1b = 0.f;
#pragma unroll
    for (int k = 0; k < 64; k += 2) {
        float xa = xsm[wid][k], xb = xsm[wid][k + 1];
        float2 wqa = Wq2[k * 32 + lane], wqb = Wq2[(k + 1) * 32 + lane];
        float2 wka = Wk2[k * 32 + lane], wkb = Wk2[(k + 1) * 32 + lane];
        float2 wva = Wv2[k * 32 + lane], wvb = Wv2[(k + 1) * 32 + lane];
        q0 += xa * wqa.x; q1 += xa * wqa.y;
        kk0 += xa * wka.x; kk1 += xa * wka.y;
        v0 += xa * wva.x; v1 += xa * wva.y;
        q0b += xb * wqb.x; q1b += xb * wqb.y;
        kk0b += xb * wkb.x; kk1b += xb * wkb.y;
        v0b += xb * wvb.x; v1b += xb * wvb.y;
    }
    q0 += q0b; q1 += q1b; kk0 += kk0b; kk1 += kk1b; v0 += v0b; v1 += v1b;
    ksm[el][s][2 * lane] = kk0; ksm[el][s][2 * lane + 1] = kk1;
    vsm[el][s][2 * lane] = v0;  vsm[el][s][2 * lane + 1] = v1;
    __syncthreads();

    // scores + softmax
    float p0 = q0 * ksm[el][0][2 * lane] + q1 * ksm[el][0][2 * lane + 1];
    float p1 = q0 * ksm[el][1][2 * lane] + q1 * ksm[el][1][2 * lane + 1];
#pragma unroll
    for (int d = 16; d; d >>= 1) {
        p0 += __shfl_xor_sync(0xffffffffu, p0, d);
        p1 += __shfl_xor_sync(0xffffffffu, p1, d);
    }
    p0 *= 0.125f; p1 *= 0.125f;
    float m = fmaxf(p0, p1);
    float ea = __expf(p0 - m), eb = __expf(p1 - m);
    float inv = 1.f / (ea + eb);
    float a0 = ea * inv, a1 = eb * inv;

    float y0 = a0 * vsm[el][0][2 * lane]     + a1 * vsm[el][1][2 * lane];
    float y1 = a0 * vsm[el][0][2 * lane + 1] + a1 * vsm[el][1][2 * lane + 1];

    // stage y for Wo broadcast (xsm row reused; x stays in regs)
    xsm[wid][2 * lane] = y0;
    xsm[wid][2 * lane + 1] = y1;
    __syncwarp();

    float o0 = 0.f, o1 = 0.f, o0b = 0.f, o1b = 0.f;
#pragma unroll
    for (int k = 0; k < 64; k += 2) {
        float ya = xsm[wid][k], yb = xsm[wid][k + 1];
        float2 woa = Wo2[k * 32 + lane], wob = Wo2[(k + 1) * 32 + lane];
        o0 += ya * woa.x; o1 += ya * woa.y;
        o0b += yb * wob.x; o1b += yb * wob.y;
    }
    x0 += o0 + o0b; x1 += o1 + o1b;

    // LN1
    float msum = x0 + x1;
#pragma unroll
    for (int d = 16; d; d >>= 1) msum += __shfl_xor_sync(0xffffffffu, msum, d);
    float mean = msum * (1.f / 64.f);
    float d0 = x0 - mean, d1 = x1 - mean;
    float vsum = d0 * d0 + d1 * d1;
#pragma unroll
    for (int d = 16; d; d >>= 1) vsum += __shfl_xor_sync(0xffffffffu, vsum, d);
    float rstd = rsqrtf(vsum * (1.f / 64.f) + 1e-5f);
    x0 = d0 * rstd; x1 = d1 * rstd;

    __syncwarp();
    xsm[wid][2 * lane] = x0;
    xsm[wid][2 * lane + 1] = x1;
    __syncwarp();

    // FFN up: 8 independent chains, lane owns f = j*32+lane
    float h[8];
#pragma unroll
    for (int j = 0; j < 8; j++) h[j] = 0.f;
#pragma unroll 8
    for (int k = 0; k < 64; k++) {
        float xk = xsm[wid][k];
        const float* w1r = W1 + k * FFN_D + lane;
#pragma unroll
        for (int j = 0; j < 8; j++) h[j] += xk * w1r[j * 32];
    }
#pragma unroll
    for (int j = 0; j < 8; j++) hsm[wid][j * 32 + lane] = fmaxf(h[j], 0.f);
    __syncwarp();

    // FFN down: split chains
    float o20 = 0.f, o21 = 0.f, o20b = 0.f, o21b = 0.f;
#pragma unroll 8
    for (int f = 0; f < FFN_D; f += 2) {
        float ha = hsm[wid][f], hb = hsm[wid][f + 1];
        float2 w2a = W22[f * 32 + lane], w2b = W22[(f + 1) * 32 + lane];
        o20 += ha * w2a.x; o21 += ha * w2a.y;
        o20b += hb * w2b.x; o21b += hb * w2b.y;
    }
    float z0 = x0 + o20 + o20b, z1 = x1 + o21 + o21b;

    // LN2 + store
    msum = z0 + z1;
#pragma unroll
    for (int d = 16; d; d >>= 1) msum += __shfl_xor_sync(0xffffffffu, msum, d);
    mean = msum * (1.f / 64.f);
    d0 = z0 - mean; d1 = z1 - mean;
    vsum = d0 * d0 + d1 * d1;
#pragma unroll
    for (int d = 16; d; d >>= 1) vsum += __shfl_xor_sync(0xffffffffu, vsum, d);
    rstd = rsqrtf(vsum * (1.f / 64.f) + 1e-5f);
    float2* gx2 = (float2*)g_x;
    gx2[(e * 2 + s) * 32 + lane] = make_float2(d0 * rstd, d1 * rstd);
}

// ---------------- K4: lm head, tf32 mma.sync, fragment-major smem, 4x2 warp grid ----------------
// A frags: As[rt=8][ks=8][128]  (16-row tiles; within: half*64 + g*8 + tig*2 + hi)
// B frags: Bs[nt=16][ks=8][64]  (8-col tiles;  within: g*8 + tig*2 + hi)
// Warp w: rows (w>>1)*32, cols (w&1)*64 -> 2 m-tiles x 8 n-tiles.
#define SMEM_K4 ((8192 + 8192 + 128) * 4)

template <bool STORE>
__global__ __launch_bounds__(256) void k4_tc(const float* __restrict__ lmW,
                                             const float* __restrict__ lmb,
                                             float* __restrict__ out) {
    extern __shared__ uint32_t dsm[];
    uint32_t* As = dsm;
    uint32_t* Bs = dsm + 8192;
    float* bsm = (float*)(dsm + 16384);

    int tid = threadIdx.x;
    int cb = blockIdx.x * 128, rb = blockIdx.y * 128;

    for (int i = tid; i < 8192; i += 256) {
        int r = i >> 6, k = i & 63;
        float v = g_x[(rb + r) * 64 + k];
        uint32_t u; asm("cvt.rna.tf32.f32 %0, %1;" : "=r"(u) : "f"(v));
        int rt = r >> 4, r16 = r & 15, half = r16 >> 3, gg = r16 & 7;
        int ks = k >> 3, k8 = k & 7, hi = k8 >> 2, tg = k8 & 3;
        As[(rt * 8 + ks) * 128 + half * 64 + gg * 8 + tg * 2 + hi] = u;
    }
    for (int i = tid; i < 8192; i += 256) {
        int n = i & 127, k = i >> 7;
        float v = lmW[(size_t)k * VOCAB + cb + n];
        uint32_t u; asm("cvt.rna.tf32.f32 %0, %1;" : "=r"(u) : "f"(v));
        int nt = n >> 3, gg = n & 7, ks = k >> 3, k8 = k & 7, hi = k8 >> 2, tg = k8 & 3;
        Bs[(nt * 8 + ks) * 64 + gg * 8 + tg * 2 + hi] = u;
    }
    if (tid < 128) bsm[tid] = lmb[cb + tid];
    __syncthreads();

    int lane = tid & 31, warp = tid >> 5;
    int wm = warp >> 1, wn = warp & 1;
    int g = lane >> 2, tig = lane & 3;

    float acc[2][8][4];
#pragma unroll
    for (int mt = 0; mt < 2; mt++)
#pragma unroll
        for (int nt = 0; nt < 8; nt++)
#pragma unroll
            for (int j = 0; j < 4; j++) acc[mt][nt][j] = 0.f;

#pragma unroll
    for (int ks = 0; ks < 8; ks++) {
        uint32_t a[2][4];
#pragma unroll
        for (int mt = 0; mt < 2; mt++) {
            const uint32_t* ap = As + ((wm * 2 + mt) * 8 + ks) * 128;
            uint2 p0 = *(const uint2*)(ap + lane * 2);        // a0, a2
            uint2 p1 = *(const uint2*)(ap + 64 + lane * 2);   // a1, a3
            a[mt][0] = p0.x; a[mt][2] = p0.y; a[mt][1] = p1.x; a[mt][3] = p1.y;
        }
#pragma unroll
        for (int nt = 0; nt < 8; nt++) {
            const uint32_t* bp = Bs + ((wn * 8 + nt) * 8 + ks) * 64;
            uint2 bb = *(const uint2*)(bp + lane * 2);
#pragma unroll
            for (int mt = 0; mt < 2; mt++) {
                asm volatile(
                    "mma.sync.aligned.m16n8k8.row.col.f32.tf32.tf32.f32 "
                    "{%0,%1,%2,%3}, {%4,%5,%6,%7}, {%8,%9}, {%0,%1,%2,%3};\n"
                    : "+f"(acc[mt][nt][0]), "+f"(acc[mt][nt][1]),
                      "+f"(acc[mt][nt][2]), "+f"(acc[mt][nt][3])
                    : "r"(a[mt][0]), "r"(a[mt][1]), "r"(a[mt][2]), "r"(a[mt][3]),
                      "r"(bb.x), "r"(bb.y));
            }
        }
    }

    if (STORE) {
#pragma unroll
        for (int mt = 0; mt < 2; mt++) {
            int r_lo = rb + wm * 32 + mt * 16 + g, r_hi = r_lo + 8;
            float inv_lo = 1.f / g_rowsum[r_lo];
            float inv_hi = 1.f / g_rowsum[r_hi];
#pragma unroll
            for (int nt = 0; nt < 8; nt++) {
                int c = wn * 64 + nt * 8 + 2 * tig;
                float b0v = bsm[c], b1v = bsm[c + 1];
                float e0 = __expf(acc[mt][nt][0] + b0v) * inv_lo;
                float e1 = __expf(acc[mt][nt][1] + b1v) * inv_lo;
                float e2 = __expf(acc[mt][nt][2] + b0v) * inv_hi;
                float e3 = __expf(acc[mt][nt][3] + b1v) * inv_hi;
                size_t base = (size_t)LBL_OFF + (size_t)cb + c;
                *(float2*)&out[base + (size_t)r_lo * VOCAB] = make_float2(e0, e1);
                *(float2*)&out[base + (size_t)r_hi * VOCAB] = make_float2(e2, e3);
            }
        }
    } else {
#pragma unroll
        for (int mt = 0; mt < 2; mt++) {
            float slo = 0.f, shi = 0.f;
#pragma unroll
            for (int nt = 0; nt < 8; nt++) {
                int c = wn * 64 + nt * 8 + 2 * tig;
                float b0v = bsm[c], b1v = bsm[c + 1];
                slo += __expf(acc[mt][nt][0] + b0v) + __expf(acc[mt][nt][1] + b1v);
                shi += __expf(acc[mt][nt][2] + b0v) + __expf(acc[mt][nt][3] + b1v);
            }
            slo += __shfl_xor_sync(0xffffffffu, slo, 1);
            slo += __shfl_xor_sync(0xffffffffu, slo, 2);
            shi += __shfl_xor_sync(0xffffffffu, shi, 1);
            shi += __shfl_xor_sync(0xffffffffu, shi, 2);
            if (tig == 0) {
                int r_lo = rb + wm * 32 + mt * 16 + g;
                atomicAdd(&g_rowsum[r_lo], slo);
                atomicAdd(&g_rowsum[r_lo + 8], shi);
            }
        }
    }
}

// ---------------- K6: labels ----------------
__global__ void k6_labels(const int* __restrict__ edge_tokens, float* __restrict__ out) {
    int idx = blockIdx.x * 256 + threadIdx.x;
    if (idx < N_EDGES * L_TOK) {
        int e = idx >> 3;
        int tok = edge_tokens[idx];
        int lab = (e == 0 && tok >= 4) ? tok : -100;
        out[idx] = (float)lab;
    }
}

// ---------------- launch ----------------
extern "C" void kernel_launch(void* const* d_in, const int* in_sizes, int n_in,
                              void* d_out, int out_size) {
    const int*   node_tokens = (const int*)d_in[0];
    const int*   edge_tokens = (const int*)d_in[1];
    const int*   edge_index  = (const int*)d_in[2];
    const float* emb    = (const float*)d_in[3];
    const float* W_self = (const float*)d_in[4];
    const float* W_nbr  = (const float*)d_in[5];
    const float* Wq     = (const float*)d_in[6];
    const float* Wk     = (const float*)d_in[7];
    const float* Wv     = (const float*)d_in[8];
    const float* Wo     = (const float*)d_in[9];
    const float* W1     = (const float*)d_in[10];
    const float* W2     = (const float*)d_in[11];
    const float* lmW    = (const float*)d_in[12];
    const float* lmb    = (const float*)d_in[13];
    float* out = (float*)d_out;

    cudaFuncSetAttribute(k4_tc<false>, cudaFuncAttributeMaxDynamicSharedMemorySize, SMEM_K4);
    cudaFuncSetAttribute(k4_tc<true>,  cudaFuncAttributeMaxDynamicSharedMemorySize, SMEM_K4);

    k0_zero<<<2080, 128>>>(edge_index);
    k1_msg<<<128, 128>>>(node_tokens, edge_tokens, edge_index, emb, W_nbr);
    k2_h<<<256, 128>>>(node_tokens, edge_index, emb, W_self);
    k3_xform<<<512, 256>>>(Wq, Wk, Wv, Wo, W1, W2);
    k4_tc<false><<<dim3(250, 32), 256, SMEM_K4>>>(lmW, lmb, out);
    k4_tc<true><<<dim3(250, 32), 256, SMEM_K4>>>(lmW, lmb, out);
    k6_labels<<<64, 256>>>(edge_tokens, out);
}

// round 5
// speedup vs baseline: 1.0776x; 1.0776x over previous
#include <cuda_runtime.h>
#include <cstdint>

#define N_NODES 100000
#define N_EDGES 2048
#define L_TOK 8
#define HID 64
#define D_IN 512      // L_TOK * HID
#define D_GNN 128
#define VOCAB 32000
#define FFN_D 256
#define NROWS (N_EDGES * 2)   // 4096 lm-head rows
#define LBL_OFF 16384         // labels occupy [0, 16384)

// ---------------- device scratch (no allocations allowed) ----------------
__device__ float g_agg[N_NODES * D_GNN];    // only dst rows ever touched
__device__ float g_edge_h[N_EDGES * D_GNN];
__device__ float g_x[NROWS * HID];
__device__ float g_rowsum[NROWS];

// ---------------- K0: zero touched agg rows + row sums ----------------
__global__ void k0_zero(const int* __restrict__ edge_index) {
    int b = blockIdx.x, t = threadIdx.x;
    if (b < N_EDGES) {
        int dst = edge_index[N_EDGES + b];
        g_agg[dst * D_GNN + t] = 0.f;
    } else {
        int i = (b - N_EDGES) * 128 + t;
        if (i < NROWS) g_rowsum[i] = 0.f;
    }
}

// ---------------- K1: msg = (node_emb[src] + edge_emb) @ W_nbr; scatter-add at dst ----------------
__global__ void k1_msg(const int* __restrict__ node_tokens,
                       const int* __restrict__ edge_tokens,
                       const int* __restrict__ edge_index,
                       const float* __restrict__ emb,
                       const float* __restrict__ W_nbr) {
    __shared__ float t_s[16][D_IN];
    __shared__ int s_src[16], s_dst[16];
    int b = blockIdx.x, tid = threadIdx.x;
    int e0 = b * 16;
    if (tid < 16) {
        s_src[tid] = edge_index[e0 + tid];
        s_dst[tid] = edge_index[N_EDGES + e0 + tid];
    }
    __syncthreads();
    for (int el = 0; el < 16; el++) {
        int e = e0 + el;
        int sn = s_src[el];
        for (int idx = tid; idx < D_IN; idx += 128) {
            int l = idx >> 6, h = idx & 63;
            int tn = node_tokens[sn * L_TOK + l];
            int te = edge_tokens[e * L_TOK + l];
            t_s[el][idx] = emb[tn * HID + h] + emb[te * HID + h];
        }
    }
    __syncthreads();
    float acc[16];
#pragma unroll
    for (int el = 0; el < 16; el++) acc[el] = 0.f;
    for (int k = 0; k < D_IN; k++) {
        float w = W_nbr[k * D_GNN + tid];
#pragma unroll
        for (int el = 0; el < 16; el++) acc[el] += t_s[el][k] * w;
    }
#pragma unroll
    for (int el = 0; el < 16; el++)
        atomicAdd(&g_agg[s_dst[el] * D_GNN + tid], acc[el]);
}

// ---------------- K2: h = relu(node_emb @ W_self + agg) at endpoints; edge_h = h_src+h_dst ----------------
__global__ void k2_h(const int* __restrict__ node_tokens,
                     const int* __restrict__ edge_index,
                     const float* __restrict__ emb,
                     const float* __restrict__ W_self) {
    __shared__ float ne[16][D_IN];
    __shared__ int s_node[16];
    int b = blockIdx.x, tid = threadIdx.x;
    int e0 = b * 8;
    if (tid < 16) {
        int el = tid & 7;
        s_node[tid] = (tid < 8) ? edge_index[e0 + el] : edge_index[N_EDGES + e0 + el];
    }
    __syncthreads();
    for (int r = 0; r < 16; r++) {
        int n = s_node[r];
        for (int idx = tid; idx < D_IN; idx += 128) {
            int l = idx >> 6, h = idx & 63;
            int tn = node_tokens[n * L_TOK + l];
            ne[r][idx] = emb[tn * HID + h];
        }
    }
    __syncthreads();
    float acc[16];
#pragma unroll
    for (int r = 0; r < 16; r++) acc[r] = 0.f;
    for (int k = 0; k < D_IN; k++) {
        float w = W_self[k * D_GNN + tid];
#pragma unroll
        for (int r = 0; r < 16; r++) acc[r] += ne[r][k] * w;
    }
#pragma unroll
    for (int el = 0; el < 8; el++) {
        float hs = fmaxf(acc[el]     + g_agg[s_node[el]     * D_GNN + tid], 0.f);
        float hd = fmaxf(acc[el + 8] + g_agg[s_node[el + 8] * D_GNN + tid], 0.f);
        g_edge_h[(e0 + el) * D_GNN + tid] = hs + hd;
    }
}

// ---------------- K3: transformer block — warp per (edge,seq) row ----------------
__global__ __launch_bounds__(256) void k3_xform(const float* __restrict__ Wq, const float* __restrict__ Wk,
                                                const float* __restrict__ Wv, const float* __restrict__ Wo,
                                                const float* __restrict__ W1, const float* __restrict__ W2) {
    __shared__ float xsm[8][64];
    __shared__ float ksm[4][2][64];
    __shared__ float vsm[4][2][64];
    __shared__ float hsm[8][FFN_D];
    int tid = threadIdx.x, lane = tid & 31, wid = tid >> 5;
    int el = wid >> 1, s = wid & 1;
    int e = blockIdx.x * 4 + el;

    const float2* xg = (const float2*)g_edge_h;
    float2 xv = xg[e * 64 + s * 32 + lane];
    float x0 = xv.x, x1 = xv.y;
    xsm[wid][2 * lane] = x0;
    xsm[wid][2 * lane + 1] = x1;
    __syncwarp();

    const float2* Wq2 = (const float2*)Wq;
    const float2* Wk2 = (const float2*)Wk;
    const float2* Wv2 = (const float2*)Wv;
    const float2* Wo2 = (const float2*)Wo;
    const float2* W22 = (const float2*)W2;

    float q0 = 0.f, q1 = 0.f, kk0 = 0.f, kk1 = 0.f, v0 = 0.f, v1 = 0.f;
    float q0b = 0.f, q1b = 0.f, kk0b = 0.f, kk1b = 0.f, v0b = 0.f, v1b = 0.f;
#pragma unroll
    for (int k = 0; k < 64; k += 2) {
        float xa = xsm[wid][k], xb = xsm[wid][k + 1];
        float2 wqa = Wq2[k * 32 + lane], wqb = Wq2[(k + 1) * 32 + lane];
        float2 wka = Wk2[k * 32 + lane], wkb = Wk2[(k + 1) * 32 + lane];
        float2 wva = Wv2[k * 32 + lane], wvb = Wv2[(k + 1) * 32 + lane];
        q0 += xa * wqa.x; q1 += xa * wqa.y;
        kk0 += xa * wka.x; kk1 += xa * wka.y;
        v0 += xa * wva.x; v1 += xa * wva.y;
        q0b += xb * wqb.x; q1b += xb * wqb.y;
        kk0b += xb * wkb.x; kk1b += xb * wkb.y;
        v0b += xb * wvb.x; v1b += xb * wvb.y;
    }
    q0 += q0b; q1 += q1b; kk0 += kk0b; kk1 += kk1b; v0 += v0b; v1 += v1b;
    ksm[el][s][2 * lane] = kk0; ksm[el][s][2 * lane + 1] = kk1;
    vsm[el][s][2 * lane] = v0;  vsm[el][s][2 * lane + 1] = v1;
    __syncthreads();

    float p0 = q0 * ksm[el][0][2 * lane] + q1 * ksm[el][0][2 * lane + 1];
    float p1 = q0 * ksm[el][1][2 * lane] + q1 * ksm[el][1][2 * lane + 1];
#pragma unroll
    for (int d = 16; d; d >>= 1) {
        p0 += __shfl_xor_sync(0xffffffffu, p0, d);
        p1 += __shfl_xor_sync(0xffffffffu, p1, d);
    }
    p0 *= 0.125f; p1 *= 0.125f;
    float m = fmaxf(p0, p1);
    float ea = __expf(p0 - m), eb = __expf(p1 - m);
    float inv = 1.f / (ea + eb);
    float a0 = ea * inv, a1 = eb * inv;

    float y0 = a0 * vsm[el][0][2 * lane]     + a1 * vsm[el][1][2 * lane];
    float y1 = a0 * vsm[el][0][2 * lane + 1] + a1 * vsm[el][1][2 * lane + 1];

    xsm[wid][2 * lane] = y0;
    xsm[wid][2 * lane + 1] = y1;
    __syncwarp();

    float o0 = 0.f, o1 = 0.f, o0b = 0.f, o1b = 0.f;
#pragma unroll
    for (int k = 0; k < 64; k += 2) {
        float ya = xsm[wid][k], yb = xsm[wid][k + 1];
        float2 woa = Wo2[k * 32 + lane], wob = Wo2[(k + 1) * 32 + lane];
        o0 += ya * woa.x; o1 += ya * woa.y;
        o0b += yb * wob.x; o1b += yb * wob.y;
    }
    x0 += o0 + o0b; x1 += o1 + o1b;

    float msum = x0 + x1;
#pragma unroll
    for (int d = 16; d; d >>= 1) msum += __shfl_xor_sync(0xffffffffu, msum, d);
    float mean = msum * (1.f / 64.f);
    float d0 = x0 - mean, d1 = x1 - mean;
    float vsum = d0 * d0 + d1 * d1;
#pragma unroll
    for (int d = 16; d; d >>= 1) vsum += __shfl_xor_sync(0xffffffffu, vsum, d);
    float rstd = rsqrtf(vsum * (1.f / 64.f) + 1e-5f);
    x0 = d0 * rstd; x1 = d1 * rstd;

    __syncwarp();
    xsm[wid][2 * lane] = x0;
    xsm[wid][2 * lane + 1] = x1;
    __syncwarp();

    float h[8];
#pragma unroll
    for (int j = 0; j < 8; j++) h[j] = 0.f;
#pragma unroll 8
    for (int k = 0; k < 64; k++) {
        float xk = xsm[wid][k];
        const float* w1r = W1 + k * FFN_D + lane;
#pragma unroll
        for (int j = 0; j < 8; j++) h[j] += xk * w1r[j * 32];
    }
#pragma unroll
    for (int j = 0; j < 8; j++) hsm[wid][j * 32 + lane] = fmaxf(h[j], 0.f);
    __syncwarp();

    float o20 = 0.f, o21 = 0.f, o20b = 0.f, o21b = 0.f;
#pragma unroll 8
    for (int f = 0; f < FFN_D; f += 2) {
        float ha = hsm[wid][f], hb = hsm[wid][f + 1];
        float2 w2a = W22[f * 32 + lane], w2b = W22[(f + 1) * 32 + lane];
        o20 += ha * w2a.x; o21 += ha * w2a.y;
        o20b += hb * w2b.x; o21b += hb * w2b.y;
    }
    float z0 = x0 + o20 + o20b, z1 = x1 + o21 + o21b;

    msum = z0 + z1;
#pragma unroll
    for (int d = 16; d; d >>= 1) msum += __shfl_xor_sync(0xffffffffu, msum, d);
    mean = msum * (1.f / 64.f);
    d0 = z0 - mean; d1 = z1 - mean;
    vsum = d0 * d0 + d1 * d1;
#pragma unroll
    for (int d = 16; d; d >>= 1) vsum += __shfl_xor_sync(0xffffffffu, vsum, d);
    rstd = rsqrtf(vsum * (1.f / 64.f) + 1e-5f);
    float2* gx2 = (float2*)g_x;
    gx2[(e * 2 + s) * 32 + lane] = make_float2(d0 * rstd, d1 * rstd);
}

// ---------------- K4: lm head, tf32 mma.sync — SINGLE pass: store exp + rowsum ----------------
// A frags: As[rt=8][ks=8][128]; B frags: Bs[nt=16][ks=8][64]; warp grid 4x2.
#define SMEM_K4 ((8192 + 8192 + 128) * 4)

__global__ __launch_bounds__(256) void k4_tc(const float* __restrict__ lmW,
                                             const float* __restrict__ lmb,
                                             float* __restrict__ out) {
    extern __shared__ uint32_t dsm[];
    uint32_t* As = dsm;
    uint32_t* Bs = dsm + 8192;
    float* bsm = (float*)(dsm + 16384);

    int tid = threadIdx.x;
    int cb = blockIdx.x * 128, rb = blockIdx.y * 128;

    for (int i = tid; i < 8192; i += 256) {
        int r = i >> 6, k = i & 63;
        float v = g_x[(rb + r) * 64 + k];
        uint32_t u; asm("cvt.rna.tf32.f32 %0, %1;" : "=r"(u) : "f"(v));
        int rt = r >> 4, r16 = r & 15, half = r16 >> 3, gg = r16 & 7;
        int ks = k >> 3, k8 = k & 7, hi = k8 >> 2, tg = k8 & 3;
        As[(rt * 8 + ks) * 128 + half * 64 + gg * 8 + tg * 2 + hi] = u;
    }
    for (int i = tid; i < 8192; i += 256) {
        int n = i & 127, k = i >> 7;
        float v = lmW[(size_t)k * VOCAB + cb + n];
        uint32_t u; asm("cvt.rna.tf32.f32 %0, %1;" : "=r"(u) : "f"(v));
        int nt = n >> 3, gg = n & 7, ks = k >> 3, k8 = k & 7, hi = k8 >> 2, tg = k8 & 3;
        Bs[(nt * 8 + ks) * 64 + gg * 8 + tg * 2 + hi] = u;
    }
    if (tid < 128) bsm[tid] = lmb[cb + tid];
    __syncthreads();

    int lane = tid & 31, warp = tid >> 5;
    int wm = warp >> 1, wn = warp & 1;
    int g = lane >> 2, tig = lane & 3;

    float acc[2][8][4];
#pragma unroll
    for (int mt = 0; mt < 2; mt++)
#pragma unroll
        for (int nt = 0; nt < 8; nt++)
#pragma unroll
            for (int j = 0; j < 4; j++) acc[mt][nt][j] = 0.f;

#pragma unroll
    for (int ks = 0; ks < 8; ks++) {
        uint32_t a[2][4];
#pragma unroll
        for (int mt = 0; mt < 2; mt++) {
            const uint32_t* ap = As + ((wm * 2 + mt) * 8 + ks) * 128;
            uint2 p0 = *(const uint2*)(ap + lane * 2);
            uint2 p1 = *(const uint2*)(ap + 64 + lane * 2);
            a[mt][0] = p0.x; a[mt][2] = p0.y; a[mt][1] = p1.x; a[mt][3] = p1.y;
        }
#pragma unroll
        for (int nt = 0; nt < 8; nt++) {
            const uint32_t* bp = Bs + ((wn * 8 + nt) * 8 + ks) * 64;
            uint2 bb = *(const uint2*)(bp + lane * 2);
#pragma unroll
            for (int mt = 0; mt < 2; mt++) {
                asm volatile(
                    "mma.sync.aligned.m16n8k8.row.col.f32.tf32.tf32.f32 "
                    "{%0,%1,%2,%3}, {%4,%5,%6,%7}, {%8,%9}, {%0,%1,%2,%3};\n"
                    : "+f"(acc[mt][nt][0]), "+f"(acc[mt][nt][1]),
                      "+f"(acc[mt][nt][2]), "+f"(acc[mt][nt][3])
                    : "r"(a[mt][0]), "r"(a[mt][1]), "r"(a[mt][2]), "r"(a[mt][3]),
                      "r"(bb.x), "r"(bb.y));
            }
        }
    }

    // epilogue: exp + store (unnormalized) + rowsum atomics
#pragma unroll
    for (int mt = 0; mt < 2; mt++) {
        int r_lo = rb + wm * 32 + mt * 16 + g, r_hi = r_lo + 8;
        float slo = 0.f, shi = 0.f;
#pragma unroll
        for (int nt = 0; nt < 8; nt++) {
            int c = wn * 64 + nt * 8 + 2 * tig;
            float b0v = bsm[c], b1v = bsm[c + 1];
            float e0 = __expf(acc[mt][nt][0] + b0v);
            float e1 = __expf(acc[mt][nt][1] + b1v);
            float e2 = __expf(acc[mt][nt][2] + b0v);
            float e3 = __expf(acc[mt][nt][3] + b1v);
            slo += e0 + e1;
            shi += e2 + e3;
            size_t base = (size_t)LBL_OFF + (size_t)cb + c;
            *(float2*)&out[base + (size_t)r_lo * VOCAB] = make_float2(e0, e1);
            *(float2*)&out[base + (size_t)r_hi * VOCAB] = make_float2(e2, e3);
        }
        slo += __shfl_xor_sync(0xffffffffu, slo, 1);
        slo += __shfl_xor_sync(0xffffffffu, slo, 2);
        shi += __shfl_xor_sync(0xffffffffu, shi, 1);
        shi += __shfl_xor_sync(0xffffffffu, shi, 2);
        if (tig == 0) {
            atomicAdd(&g_rowsum[r_lo], slo);
            atomicAdd(&g_rowsum[r_hi], shi);
        }
    }
}

// ---------------- K5: in-place normalization (float4 RMW) ----------------
__global__ __launch_bounds__(256) void k5_norm(float* __restrict__ out) {
    int row = blockIdx.x;
    float inv = 1.f / g_rowsum[row];
    float4* p = (float4*)(out + (size_t)LBL_OFF + (size_t)row * VOCAB);
    for (int i = threadIdx.x; i < VOCAB / 4; i += 256) {
        float4 v = p[i];
        v.x *= inv; v.y *= inv; v.z *= inv; v.w *= inv;
        p[i] = v;
    }
}

// ---------------- K6: labels ----------------
__global__ void k6_labels(const int* __restrict__ edge_tokens, float* __restrict__ out) {
    int idx = blockIdx.x * 256 + threadIdx.x;
    if (idx < N_EDGES * L_TOK) {
        int e = idx >> 3;
        int tok = edge_tokens[idx];
        int lab = (e == 0 && tok >= 4) ? tok : -100;
        out[idx] = (float)lab;
    }
}

// ---------------- launch ----------------
extern "C" void kernel_launch(void* const* d_in, const int* in_sizes, int n_in,
                              void* d_out, int out_size) {
    const int*   node_tokens = (const int*)d_in[0];
    const int*   edge_tokens = (const int*)d_in[1];
    const int*   edge_index  = (const int*)d_in[2];
    const float* emb    = (const float*)d_in[3];
    const float* W_self = (const float*)d_in[4];
    const float* W_nbr  = (const float*)d_in[5];
    const float* Wq     = (const float*)d_in[6];
    const float* Wk     = (const float*)d_in[7];
    const float* Wv     = (const float*)d_in[8];
    const float* Wo     = (const float*)d_in[9];
    const float* W1     = (const float*)d_in[10];
    const float* W2     = (const float*)d_in[11];
    const float* lmW    = (const float*)d_in[12];
    const float* lmb    = (const float*)d_in[13];
    float* out = (float*)d_out;

    cudaFuncSetAttribute(k4_tc, cudaFuncAttributeMaxDynamicSharedMemorySize, SMEM_K4);

    k0_zero<<<2080, 128>>>(edge_index);
    k1_msg<<<128, 128>>>(node_tokens, edge_tokens, edge_index, emb, W_nbr);
    k2_h<<<256, 128>>>(node_tokens, edge_index, emb, W_self);
    k3_xform<<<512, 256>>>(Wq, Wk, Wv, Wo, W1, W2);
    k4_tc<<<dim3(250, 32), 256, SMEM_K4>>>(lmW, lmb, out);
    k5_norm<<<4096, 256>>>(out);
    k6_labels<<<64, 256>>>(edge_tokens, out);
}